// round 6
// baseline (speedup 1.0000x reference)
#include <cuda_runtime.h>
#include <cuda_bf16.h>
#include <cuda_fp16.h>
#include <cstdint>

// HeadVQ via legacy warp-MMA (mma.sync bf16 + ldmatrix + cp.async; harness PTX
// target rejects tcgen05). Per CTA: 128 rows x 512 codes, 4 warps x 32 rows.
// 32 rows/warp doubles B-fragment reuse per ldmatrix (the R5 bottleneck was
// smem crossbar at L1=55%). Warp-private argmin/candidate/rescore pipeline.
//
// Output layout (float32):
//   [0, 16777216)          K_mix
//   [16777216, 33554432)   V_mix
//   [+0..3]                0.25*mse_k, 0.25*mse_v, 0.25*mse_k, 0.25*mse_v
//   [+4, +516)             usage_k
//   [+516, +1028)          usage_v

#define DDIM     128
#define NCODES   512
#define TILE_M   128
#define TPB      128
#define NWARP    4
#define CHUNK    64
#define NCHUNK   8
#define MARGIN   0.03f
#define FILTSL   0.002f
#define MAXCW    384          // per-warp candidate capacity (expect ~38)

#define PADB     272          // bytes per padded bf16 row (136 bf16)

// ---- SMEM layout (bytes) ----
#define OFF_A      0          // 128 * 272 = 34816
#define OFF_B      34816      // 2 * 17408 = 34816
#define BBUF       17408
#define OFF_C2     69632      // 2048
#define OFF_THR    71680      // 512
#define OFF_FINK   72192      // 1024
#define OFF_Z2     73216      // 512
#define OFF_CANDN  73728      // 16
#define OFF_CAND   73744      // 4 * 384 * 4 = 6144
#define SMEM_TOTAL 79888

// ---- global scratch ----
__device__ __nv_bfloat16 g_cbB[2][NCODES * DDIM];
__device__ float         g_c2[2 * NCODES];
__device__ unsigned int  g_counts[2 * NCODES];
__device__ float         g_sse[2];

// ---- helpers ----
__device__ __forceinline__ uint32_t smem_u32(const void* p) {
    uint32_t a;
    asm("{ .reg .u64 t; cvta.to.shared.u64 t, %1; cvt.u32.u64 %0, t; }" : "=r"(a) : "l"(p));
    return a;
}
__device__ __forceinline__ uint32_t mapf(float s) {
    uint32_t u = __float_as_uint(s);
    return (u & 0x80000000u) ? ~u : (u | 0x80000000u);
}
__device__ __forceinline__ float unmapf(uint32_t m) {
    uint32_t u = (m & 0x80000000u) ? (m ^ 0x80000000u) : ~m;
    return __uint_as_float(u);
}
__device__ __forceinline__ uint32_t bf2(float lo, float hi) {
    uint32_t r;
    asm("cvt.rn.satfinite.bf16x2.f32 %0, %1, %2;" : "=r"(r) : "f"(hi), "f"(lo));
    return r;
}
__device__ __forceinline__ void cpasync16(uint32_t dst, const void* src) {
    asm volatile("cp.async.cg.shared.global [%0], [%1], 16;" :: "r"(dst), "l"(src));
}
#define CP_COMMIT() asm volatile("cp.async.commit_group;" ::: "memory")
#define CP_WAIT0()  asm volatile("cp.async.wait_group 0;" ::: "memory")

__device__ __forceinline__ void ldsm4(uint32_t* r, uint32_t addr) {
    asm volatile("ldmatrix.sync.aligned.m8n8.x4.shared.b16 {%0,%1,%2,%3}, [%4];"
                 : "=r"(r[0]), "=r"(r[1]), "=r"(r[2]), "=r"(r[3]) : "r"(addr));
}
__device__ __forceinline__ void mma16816(float* c, const uint32_t* a, const uint32_t* b) {
    asm volatile(
        "mma.sync.aligned.m16n8k16.row.col.f32.bf16.bf16.f32 "
        "{%0,%1,%2,%3}, {%4,%5,%6,%7}, {%8,%9}, {%0,%1,%2,%3};"
        : "+f"(c[0]), "+f"(c[1]), "+f"(c[2]), "+f"(c[3])
        : "r"(a[0]), "r"(a[1]), "r"(a[2]), "r"(a[3]), "r"(b[0]), "r"(b[1]));
}

// ---- prep: codebooks -> bf16 + c2 ----
__global__ void prep_kernel(const float* __restrict__ CBk, const float* __restrict__ CBv) {
    int n = blockIdx.x, q = blockIdx.y, k = threadIdx.x;  // grid(512,2), 128 thr
    const float* src = q ? CBv : CBk;
    float v = src[n * DDIM + k];
    float s = v * v;
    #pragma unroll
    for (int o = 16; o; o >>= 1) s += __shfl_xor_sync(0xffffffffu, s, o);
    __shared__ float red[4];
    if ((k & 31) == 0) red[k >> 5] = s;
    __syncthreads();
    if (k == 0) g_c2[q * NCODES + n] = red[0] + red[1] + red[2] + red[3];
    g_cbB[q][n * DDIM + k] = __float2bfloat16(v);
}

__global__ void zero_kernel() {
    int t = threadIdx.x;
    if (t < 2 * NCODES) g_counts[t] = 0u;
    if (t < 2) g_sse[t] = 0.0f;
}

__global__ void dummy_kernel() {}

// ---- main VQ kernel ----
__global__ void __launch_bounds__(TPB, 2) vq_kernel(
    const float* __restrict__ K, const float* __restrict__ V,
    const float* __restrict__ CBk, const float* __restrict__ CBv,
    float* __restrict__ OUTK, float* __restrict__ OUTV, int tiles_per_mat)
{
    extern __shared__ __align__(16) unsigned char smem[];
    const uint32_t sb = smem_u32(smem);

    const int q    = (blockIdx.x >= (unsigned)tiles_per_mat) ? 1 : 0;
    const int tile = blockIdx.x - q * tiles_per_mat;
    const float* Z   = q ? V : K;
    const float* CBf = q ? CBv : CBk;
    float*       OUT = q ? OUTV : OUTK;
    const long rowbase = (long)tile * TILE_M;

    const int t = threadIdx.x, wid = t >> 5, lane = t & 31;
    const int g = lane >> 2, qd = lane & 3;
    const int wbase = wid * 32;           // 32 rows per warp

    float*    rowthr = reinterpret_cast<float*>(smem + OFF_THR);
    unsigned long long* finkey = reinterpret_cast<unsigned long long*>(smem + OFF_FINK);
    float*    z2s   = reinterpret_cast<float*>(smem + OFF_Z2);
    float*    c2sm  = reinterpret_cast<float*>(smem + OFF_C2);
    uint32_t* cand  = reinterpret_cast<uint32_t*>(smem + OFF_CAND) + wid * MAXCW;
    uint32_t* candn = reinterpret_cast<uint32_t*>(smem + OFF_CANDN);

    // ---- preamble ----
    if (t < NWARP) candn[t] = 0u;
    finkey[wbase + lane] = ~0ull;                 // warp owns rows [wbase, wbase+32)
    #pragma unroll
    for (int i = t; i < NCODES; i += TPB) c2sm[i] = g_c2[q * NCODES + i];

    // A: fp32 -> bf16 padded smem (1 thread = 1 row) + z2; B chunk 0 cp.async
    {
        const float4* Zg4 = reinterpret_cast<const float4*>(Z + rowbase * DDIM) + t * 32;
        const uint32_t dsta = (uint32_t)(OFF_A + t * PADB);
        float z2p = 0.0f;
        #pragma unroll
        for (int j = 0; j < 16; j++) {
            float4 f0 = Zg4[2 * j], f1 = Zg4[2 * j + 1];
            uint4 pk;
            pk.x = bf2(f0.x, f0.y); pk.y = bf2(f0.z, f0.w);
            pk.z = bf2(f1.x, f1.y); pk.w = bf2(f1.z, f1.w);
            *reinterpret_cast<uint4*>(smem + dsta + j * 16) = pk;
            z2p += f0.x*f0.x + f0.y*f0.y + f0.z*f0.z + f0.w*f0.w
                 + f1.x*f1.x + f1.y*f1.y + f1.z*f1.z + f1.w*f1.w;
        }
        z2s[t] = z2p;

        const char* bsrc = reinterpret_cast<const char*>(g_cbB[q]);
        #pragma unroll
        for (int j = 0; j < 8; j++) {
            int i = t + j * TPB;                 // 1024 x 16B (64 codes)
            int r = i >> 4, c = i & 15;
            cpasync16(sb + OFF_B + r * PADB + c * 16, bsrc + r * 256 + c * 16);
        }
        CP_COMMIT();
    }
    __syncthreads();    // A tile visible to whole CTA (warps read own rows only,
                        // but B buffer reuse below needs CTA-wide ordering anyway)

    // ---- A fragments: 2 row-blocks x 8 kslices x 4 regs ----
    uint32_t afr[2][8][4];
    {
        const int mrow  = ((lane >> 3) & 1) * 8 + (lane & 7);
        const int khalf = (lane >> 4) & 1;
        #pragma unroll
        for (int rb = 0; rb < 2; rb++) {
            uint32_t abase = sb + OFF_A + (wbase + rb * 16 + mrow) * PADB + khalf * 16;
            #pragma unroll
            for (int ks = 0; ks < 8; ks++) ldsm4(afr[rb][ks], abase + ks * 32);
        }
    }

    // running per-row mins: rows {rb*16+g, rb*16+8+g} -> rm[rb*2], rm[rb*2+1]
    float rm[4] = {3.4e38f, 3.4e38f, 3.4e38f, 3.4e38f};

    // ---- main chunk loop ----
    float acc[2][8][4];
    for (int ch = 0; ch < NCHUNK; ch++) {
        const int buf = ch & 1;
        CP_WAIT0();
        __syncthreads();                 // B[buf] visible; prev buffer free

        if (ch + 1 < NCHUNK) {
            const char* bsrc = reinterpret_cast<const char*>(g_cbB[q])
                               + (ch + 1) * CHUNK * 256;
            #pragma unroll
            for (int j = 0; j < 8; j++) {
                int i = t + j * TPB;
                int r = i >> 4, c = i & 15;
                cpasync16(sb + OFF_B + (buf ^ 1) * BBUF + r * PADB + c * 16,
                          bsrc + r * 256 + c * 16);
            }
        }
        CP_COMMIT();

        // GEMM: 32 rows x 64 codes x 128 k  (each ldsm4 feeds 4 MMAs)
        #pragma unroll
        for (int rb = 0; rb < 2; rb++)
            #pragma unroll
            for (int nt = 0; nt < 8; nt++)
                #pragma unroll
                for (int i = 0; i < 4; i++) acc[rb][nt][i] = 0.0f;

        const int nrow  = ((lane >> 4) & 1) * 8 + (lane & 7);
        const int bkoff = ((lane >> 3) & 1) * 16;
        const uint32_t bbase = sb + OFF_B + buf * BBUF + nrow * PADB + bkoff;
        #pragma unroll
        for (int ks = 0; ks < 8; ks++) {
            #pragma unroll
            for (int ntp = 0; ntp < 4; ntp++) {
                uint32_t b[4];
                ldsm4(b, bbase + ntp * 16 * PADB + ks * 32);
                mma16816(acc[0][2 * ntp],     afr[0][ks], b);
                mma16816(acc[0][2 * ntp + 1], afr[0][ks], b + 2);
                mma16816(acc[1][2 * ntp],     afr[1][ks], b);
                mma16816(acc[1][2 * ntp + 1], afr[1][ks], b + 2);
            }
        }

        // scores + per-thread mins
        float m[4] = {3.4e38f, 3.4e38f, 3.4e38f, 3.4e38f};
        #pragma unroll
        for (int rb = 0; rb < 2; rb++) {
            #pragma unroll
            for (int nt = 0; nt < 8; nt++) {
                int cbase = ch * CHUNK + nt * 8 + qd * 2;
                float2 c2p = *reinterpret_cast<const float2*>(&c2sm[cbase]);
                float s0 = fmaf(-2.0f, acc[rb][nt][0], c2p.x);
                float s1 = fmaf(-2.0f, acc[rb][nt][1], c2p.y);
                float s2 = fmaf(-2.0f, acc[rb][nt][2], c2p.x);
                float s3 = fmaf(-2.0f, acc[rb][nt][3], c2p.y);
                acc[rb][nt][0] = s0; acc[rb][nt][1] = s1;
                acc[rb][nt][2] = s2; acc[rb][nt][3] = s3;
                m[rb * 2]     = fminf(m[rb * 2],     fminf(s0, s1));
                m[rb * 2 + 1] = fminf(m[rb * 2 + 1], fminf(s2, s3));
            }
        }
        #pragma unroll
        for (int off = 1; off <= 2; off <<= 1) {
            #pragma unroll
            for (int e = 0; e < 4; e++)
                m[e] = fminf(m[e], __shfl_xor_sync(0xffffffffu, m[e], off));
        }
        #pragma unroll
        for (int e = 0; e < 4; e++) rm[e] = fminf(rm[e], m[e]);

        // candidate scan vs running min (superset of final-threshold set)
        #pragma unroll
        for (int rb = 0; rb < 2; rb++) {
            float thr0 = rm[rb * 2] + MARGIN, thr1 = rm[rb * 2 + 1] + MARGIN;
            int rA = wbase + rb * 16 + g, rB = rA + 8;
            #pragma unroll
            for (int nt = 0; nt < 8; nt++) {
                int cbase = ch * CHUNK + nt * 8 + qd * 2;
                #pragma unroll
                for (int e = 0; e < 4; e++) {
                    float sc = acc[rb][nt][e];
                    int   row = (e < 2) ? rA : rB;
                    float th  = (e < 2) ? thr0 : thr1;
                    if (sc < th) {
                        int code = cbase + (e & 1);
                        uint32_t h = __half_as_ushort(__float2half_rn(sc));
                        uint32_t pos = atomicAdd(&candn[wid], 1u);
                        if (pos < MAXCW)
                            cand[pos] = ((uint32_t)row << 25) | ((uint32_t)code << 16) | h;
                    }
                }
            }
        }
    }

    // publish final per-row bf16-score min (warp-local)
    if (qd == 0) {
        rowthr[wbase + g]      = rm[0];
        rowthr[wbase + 8 + g]  = rm[1];
        rowthr[wbase + 16 + g] = rm[2];
        rowthr[wbase + 24 + g] = rm[3];
    }
    __syncwarp();

    // ---- exact fp32 rescore of this warp's candidates ----
    {
        int nc = (int)candn[wid]; if (nc > MAXCW) nc = MAXCW;
        for (int j = 0; j < nc; j++) {
            uint32_t e = cand[j];
            int crow = (int)(e >> 25);
            int code = (int)((e >> 16) & 0x1FFu);
            float sch = __half2float(__ushort_as_half((unsigned short)(e & 0xFFFFu)));
            if (sch > rowthr[crow] + MARGIN + FILTSL) continue;
            const float* zr = Z + (rowbase + crow) * DDIM;
            const float* cr = CBf + (long)code * DDIM;
            float p = 0.0f;
            #pragma unroll
            for (int kk = 0; kk < 4; kk++)
                p = fmaf(zr[lane + kk * 32], cr[lane + kk * 32], p);
            #pragma unroll
            for (int o = 16; o; o >>= 1) p += __shfl_xor_sync(0xffffffffu, p, o);
            if (lane == 0) {
                float t1 = z2s[crow] + c2sm[code];
                float d  = fmaf(-2.0f, p, t1);
                unsigned long long key =
                    ((unsigned long long)mapf(d) << 32) | (uint32_t)code;
                if (key < finkey[crow]) finkey[crow] = key;   // warp-serial
            }
        }
    }
    __syncwarp();

    // ---- finalize (lane == row within warp): idx, counts, sse, gather ----
    int idxv;
    {
        unsigned long long k = finkey[wbase + lane];
        idxv = (int)(k & 0xFFFFu);
        atomicAdd(&g_counts[q * NCODES + idxv], 1u);
        float d = unmapf((uint32_t)(k >> 32));
        #pragma unroll
        for (int o = 16; o; o >>= 1) d += __shfl_xor_sync(0xffffffffu, d, o);
        if (lane == 0) atomicAdd(&g_sse[q], d);
    }
    {
        const float4* cb4 = reinterpret_cast<const float4*>(CBf);
        float4* o4 = reinterpret_cast<float4*>(OUT + rowbase * DDIM);
        #pragma unroll
        for (int i = 0; i < 32; i++) {
            int idx_i = __shfl_sync(0xffffffffu, idxv, i);
            o4[(wbase + i) * 32 + lane] = cb4[idx_i * 32 + lane];
        }
    }
}

__global__ void fin_kernel(float* __restrict__ scal, float* __restrict__ usage,
                           float invN, float invND) {
    int t = threadIdx.x;  // 512
    usage[t]          = (float)g_counts[t] * invN;
    usage[NCODES + t] = (float)g_counts[NCODES + t] * invN;
    if (t == 0) {
        float mk = g_sse[0] * invND * 0.25f;
        float mv = g_sse[1] * invND * 0.25f;
        scal[0] = mk; scal[1] = mv; scal[2] = mk; scal[3] = mv;
    }
}

extern "C" void kernel_launch(void* const* d_in, const int* in_sizes, int n_in,
                              void* d_out, int out_size) {
    const float* K   = (const float*)d_in[0];
    const float* V   = (const float*)d_in[1];
    const float* CBk = (const float*)d_in[2];
    const float* CBv = (const float*)d_in[3];
    float* out = (float*)d_out;

    const long nK    = (long)in_sizes[0];       // 16777216
    const long nrows = nK / DDIM;               // 131072
    const int  tiles = (int)(nrows / TILE_M);   // 1024

    float* Kout  = out;
    float* Vout  = out + nK;
    float* scal  = out + 2 * nK;
    float* usage = scal + 4;

    cudaFuncSetAttribute(vq_kernel, cudaFuncAttributeMaxDynamicSharedMemorySize, SMEM_TOTAL);

    zero_kernel<<<1, 1024>>>();
    prep_kernel<<<dim3(NCODES, 2), DDIM>>>(CBk, CBv);
    dummy_kernel<<<1, 32>>>();   // keeps vq_kernel in ncu's -s 5 -c 1 window
    vq_kernel<<<2 * tiles, TPB, SMEM_TOTAL>>>(K, V, CBk, CBv, Kout, Vout, tiles);
    fin_kernel<<<1, NCODES>>>(scal, usage, 1.0f / (float)nrows, 1.0f / (float)nK);
}

// round 8
// speedup vs baseline: 1.3075x; 1.3075x over previous
#include <cuda_runtime.h>
#include <cuda_bf16.h>
#include <cuda_fp16.h>
#include <cstdint>
#include <cstring>

// HeadVQ via legacy warp-MMA. R5 skeleton (8 warps x 16 rows, TPB=256,
// 2 CTA/SM) + fp16-accumulate MMA and a half2 epilogue: scores, mins and
// threshold compares all in packed fp16. Margin-rescue (exact fp32 rescore
// of candidates within MARGIN of the running min) keeps the final argmin
// exact: superset holds while MARGIN > 2x fp16 score error (~4e-3 << 0.03).
//
// Output layout (float32):
//   [0, 16777216)          K_mix
//   [16777216, 33554432)   V_mix
//   [+0..3]                0.25*mse_k, 0.25*mse_v, 0.25*mse_k, 0.25*mse_v
//   [+4, +516)             usage_k
//   [+516, +1028)          usage_v

#define DDIM     128
#define NCODES   512
#define TILE_M   128
#define TPB      256
#define NWARP    8
#define CHUNK    64
#define NCHUNK   8
#define MARGIN   0.03f
#define FILTSL   0.002f
#define MAXCW    256

#define PADB     272          // bytes per padded fp16 row (136 halves)

// ---- SMEM layout (bytes) ----
#define OFF_A      0          // 128 * 272 = 34816
#define OFF_B      34816      // 2 * 17408 = 34816
#define BBUF       17408
#define OFF_C2     69632      // 2048 (fp32, exact rescore)
#define OFF_C2H    71680      // 1024 (half2 pairs)
#define OFF_THR    72704      // 512
#define OFF_FINK   73216      // 1024
#define OFF_Z2     74240      // 512
#define OFF_CANDN  74752      // 32
#define OFF_CAND   74784      // 8 * 256 * 4 = 8192
#define SMEM_TOTAL 82976

// ---- global scratch ----
__device__ __half        g_cbH[2][NCODES * DDIM];
__device__ float         g_c2[2 * NCODES];
__device__ unsigned int  g_counts[2 * NCODES];
__device__ float         g_sse[2];

// ---- bit-cast helpers (this CUDA version lacks __half2_as_uint) ----
__device__ __forceinline__ uint32_t h2u(__half2 h) {
    uint32_t u;
    memcpy(&u, &h, 4);
    return u;
}
__device__ __forceinline__ __half2 u2h(uint32_t u) {
    __half2 h;
    memcpy(&h, &u, 4);
    return h;
}

// ---- helpers ----
__device__ __forceinline__ uint32_t smem_u32(const void* p) {
    uint32_t a;
    asm("{ .reg .u64 t; cvta.to.shared.u64 t, %1; cvt.u32.u64 %0, t; }" : "=r"(a) : "l"(p));
    return a;
}
__device__ __forceinline__ uint32_t mapf(float s) {
    uint32_t u = __float_as_uint(s);
    return (u & 0x80000000u) ? ~u : (u | 0x80000000u);
}
__device__ __forceinline__ float unmapf(uint32_t m) {
    uint32_t u = (m & 0x80000000u) ? (m ^ 0x80000000u) : ~m;
    return __uint_as_float(u);
}
__device__ __forceinline__ void cpasync16(uint32_t dst, const void* src) {
    asm volatile("cp.async.cg.shared.global [%0], [%1], 16;" :: "r"(dst), "l"(src));
}
#define CP_COMMIT() asm volatile("cp.async.commit_group;" ::: "memory")
#define CP_WAIT0()  asm volatile("cp.async.wait_group 0;" ::: "memory")

__device__ __forceinline__ void ldsm4(uint32_t* r, uint32_t addr) {
    asm volatile("ldmatrix.sync.aligned.m8n8.x4.shared.b16 {%0,%1,%2,%3}, [%4];"
                 : "=r"(r[0]), "=r"(r[1]), "=r"(r[2]), "=r"(r[3]) : "r"(addr));
}
// fp16 x fp16 -> fp16 accumulate; D/C are 2 regs of f16x2:
// d0 = (c0,c1) -> row g,   cols 2qd, 2qd+1;  d1 = (c2,c3) -> row g+8
__device__ __forceinline__ void mma16816h(uint32_t* c, const uint32_t* a, const uint32_t* b) {
    asm volatile(
        "mma.sync.aligned.m16n8k16.row.col.f16.f16.f16.f16 "
        "{%0,%1}, {%2,%3,%4,%5}, {%6,%7}, {%0,%1};"
        : "+r"(c[0]), "+r"(c[1])
        : "r"(a[0]), "r"(a[1]), "r"(a[2]), "r"(a[3]), "r"(b[0]), "r"(b[1]));
}

// ---- prep: codebooks -> fp16 + c2 ----
__global__ void prep_kernel(const float* __restrict__ CBk, const float* __restrict__ CBv) {
    int n = blockIdx.x, q = blockIdx.y, k = threadIdx.x;  // grid(512,2), 128 thr
    const float* src = q ? CBv : CBk;
    float v = src[n * DDIM + k];
    float s = v * v;
    #pragma unroll
    for (int o = 16; o; o >>= 1) s += __shfl_xor_sync(0xffffffffu, s, o);
    __shared__ float red[4];
    if ((k & 31) == 0) red[k >> 5] = s;
    __syncthreads();
    if (k == 0) g_c2[q * NCODES + n] = red[0] + red[1] + red[2] + red[3];
    g_cbH[q][n * DDIM + k] = __float2half_rn(v);
}

__global__ void zero_kernel() {
    int t = threadIdx.x;
    if (t < 2 * NCODES) g_counts[t] = 0u;
    if (t < 2) g_sse[t] = 0.0f;
}

__global__ void dummy_kernel() {}

// ---- main VQ kernel ----
__global__ void __launch_bounds__(TPB, 2) vq_kernel(
    const float* __restrict__ K, const float* __restrict__ V,
    const float* __restrict__ CBk, const float* __restrict__ CBv,
    float* __restrict__ OUTK, float* __restrict__ OUTV, int tiles_per_mat)
{
    extern __shared__ __align__(16) unsigned char smem[];
    const uint32_t sb = smem_u32(smem);

    const int q    = (blockIdx.x >= (unsigned)tiles_per_mat) ? 1 : 0;
    const int tile = blockIdx.x - q * tiles_per_mat;
    const float* Z   = q ? V : K;
    const float* CBf = q ? CBv : CBk;
    float*       OUT = q ? OUTV : OUTK;
    const long rowbase = (long)tile * TILE_M;

    const int t = threadIdx.x, wid = t >> 5, lane = t & 31;
    const int g = lane >> 2, qd = lane & 3;
    const int wbase = wid * 16;

    float*    rowthr = reinterpret_cast<float*>(smem + OFF_THR);
    unsigned long long* finkey = reinterpret_cast<unsigned long long*>(smem + OFF_FINK);
    float*    z2s   = reinterpret_cast<float*>(smem + OFF_Z2);
    float*    c2sm  = reinterpret_cast<float*>(smem + OFF_C2);
    uint32_t* c2hm  = reinterpret_cast<uint32_t*>(smem + OFF_C2H);
    uint32_t* cand  = reinterpret_cast<uint32_t*>(smem + OFF_CAND) + wid * MAXCW;
    uint32_t* candn = reinterpret_cast<uint32_t*>(smem + OFF_CANDN);

    // ---- preamble ----
    if (t < NWARP) candn[t] = 0u;
    if (lane < 16) finkey[wbase + lane] = ~0ull;
    {   // c2: fp32 + packed half2 (one pair per thread; TPB == NCODES/2)
        float2 v = reinterpret_cast<const float2*>(g_c2 + q * NCODES)[t];
        c2sm[2 * t]     = v.x;
        c2sm[2 * t + 1] = v.y;
        c2hm[t] = h2u(__floats2half2_rn(v.x, v.y));
    }

    // A: fp32 -> fp16 padded smem (+ z2); B chunk 0 cp.async
    {
        const int row = t >> 1, half = t & 1;
        const float4* Zg4 = reinterpret_cast<const float4*>(Z + rowbase * DDIM)
                            + row * 32 + half * 16;
        const uint32_t dsta = (uint32_t)(OFF_A + row * PADB + half * 128);
        float z2p = 0.0f;
        #pragma unroll
        for (int j = 0; j < 8; j++) {
            float4 f0 = Zg4[2 * j], f1 = Zg4[2 * j + 1];
            uint4 pk;
            pk.x = h2u(__floats2half2_rn(f0.x, f0.y));
            pk.y = h2u(__floats2half2_rn(f0.z, f0.w));
            pk.z = h2u(__floats2half2_rn(f1.x, f1.y));
            pk.w = h2u(__floats2half2_rn(f1.z, f1.w));
            *reinterpret_cast<uint4*>(smem + dsta + j * 16) = pk;
            z2p += f0.x*f0.x + f0.y*f0.y + f0.z*f0.z + f0.w*f0.w
                 + f1.x*f1.x + f1.y*f1.y + f1.z*f1.z + f1.w*f1.w;
        }
        float other = __shfl_xor_sync(0xffffffffu, z2p, 1);
        if (half == 0) z2s[row] = z2p + other;

        const char* bsrc = reinterpret_cast<const char*>(g_cbH[q]);
        #pragma unroll
        for (int j = 0; j < 4; j++) {
            int i = t + j * TPB;
            int r = i >> 4, c = i & 15;
            cpasync16(sb + OFF_B + r * PADB + c * 16, bsrc + r * 256 + c * 16);
        }
        CP_COMMIT();
    }
    __syncthreads();

    // ---- A fragments (8 kslices x 4 regs), warp-local rows ----
    uint32_t afr[8][4];
    {
        const int mrow  = wbase + ((lane >> 3) & 1) * 8 + (lane & 7);
        const int khalf = (lane >> 4) & 1;
        uint32_t abase = sb + OFF_A + mrow * PADB + khalf * 16;
        #pragma unroll
        for (int ks = 0; ks < 8; ks++) ldsm4(afr[ks], abase + ks * 32);
    }

    const int row0 = wbase + g, row1 = row0 + 8;
    float rm0 = 3.4e38f, rm1 = 3.4e38f;
    const __half2 neg2 = __floats2half2_rn(-2.0f, -2.0f);

    // ---- main chunk loop ----
    uint32_t acc[8][2];
    for (int ch = 0; ch < NCHUNK; ch++) {
        const int buf = ch & 1;
        CP_WAIT0();
        __syncthreads();                 // B[buf] visible; prev buffer free

        if (ch + 1 < NCHUNK) {
            const char* bsrc = reinterpret_cast<const char*>(g_cbH[q])
                               + (ch + 1) * CHUNK * 256;
            #pragma unroll
            for (int j = 0; j < 4; j++) {
                int i = t + j * TPB;
                int r = i >> 4, c = i & 15;
                cpasync16(sb + OFF_B + (buf ^ 1) * BBUF + r * PADB + c * 16,
                          bsrc + r * 256 + c * 16);
            }
        }
        CP_COMMIT();

        // GEMM: 16 rows x 64 codes x 128 k, fp16 accumulate
        #pragma unroll
        for (int nt = 0; nt < 8; nt++) { acc[nt][0] = 0u; acc[nt][1] = 0u; }

        const int nrow  = ((lane >> 4) & 1) * 8 + (lane & 7);
        const int bkoff = ((lane >> 3) & 1) * 16;
        const uint32_t bbase = sb + OFF_B + buf * BBUF + nrow * PADB + bkoff;
        #pragma unroll
        for (int ks = 0; ks < 8; ks++) {
            #pragma unroll
            for (int ntp = 0; ntp < 4; ntp++) {
                uint32_t b[4];
                ldsm4(b, bbase + ntp * 16 * PADB + ks * 32);
                mma16816h(acc[2 * ntp],     afr[ks], b);
                mma16816h(acc[2 * ntp + 1], afr[ks], b + 2);
            }
        }

        // scores (half2) + packed mins
        __half2 s2[8][2];
        __half2 m2_0 = __floats2half2_rn(6.0e4f, 6.0e4f);
        __half2 m2_1 = m2_0;
        #pragma unroll
        for (int nt = 0; nt < 8; nt++) {
            __half2 c2p = u2h(c2hm[ch * 32 + nt * 4 + qd]);
            __half2 l0  = u2h(acc[nt][0]);
            __half2 l1  = u2h(acc[nt][1]);
            s2[nt][0] = __hfma2(l0, neg2, c2p);
            s2[nt][1] = __hfma2(l1, neg2, c2p);
            m2_0 = __hmin2(m2_0, s2[nt][0]);
            m2_1 = __hmin2(m2_1, s2[nt][1]);
        }
        #pragma unroll
        for (int off = 1; off <= 2; off <<= 1) {
            m2_0 = __hmin2(m2_0, u2h(__shfl_xor_sync(0xffffffffu, h2u(m2_0), off)));
            m2_1 = __hmin2(m2_1, u2h(__shfl_xor_sync(0xffffffffu, h2u(m2_1), off)));
        }
        rm0 = fminf(rm0, __half2float(__hmin(__low2half(m2_0), __high2half(m2_0))));
        rm1 = fminf(rm1, __half2float(__hmin(__low2half(m2_1), __high2half(m2_1))));

        // candidate scan vs running min
        const __half thrh0 = __float2half_rn(rm0 + MARGIN);
        const __half thrh1 = __float2half_rn(rm1 + MARGIN);
        #pragma unroll
        for (int nt = 0; nt < 8; nt++) {
            int cbase = ch * CHUNK + nt * 8 + qd * 2;
            #pragma unroll
            for (int p = 0; p < 2; p++) {
                __half lo = __low2half(s2[nt][p]), hi = __high2half(s2[nt][p]);
                __half th = p ? thrh1 : thrh0;
                int   row = p ? row1 : row0;
                if (__hlt(lo, th)) {
                    uint32_t pos = atomicAdd(&candn[wid], 1u);
                    if (pos < MAXCW)
                        cand[pos] = ((uint32_t)row << 25) | ((uint32_t)cbase << 16)
                                  | (uint32_t)__half_as_ushort(lo);
                }
                if (__hlt(hi, th)) {
                    uint32_t pos = atomicAdd(&candn[wid], 1u);
                    if (pos < MAXCW)
                        cand[pos] = ((uint32_t)row << 25) | ((uint32_t)(cbase + 1) << 16)
                                  | (uint32_t)__half_as_ushort(hi);
                }
            }
        }
    }

    // publish final per-row score min (warp-local)
    if (qd == 0) { rowthr[row0] = rm0; rowthr[row1] = rm1; }
    __syncwarp();

    // ---- exact fp32 rescore of this warp's candidates ----
    {
        int nc = (int)candn[wid]; if (nc > MAXCW) nc = MAXCW;
        for (int j = 0; j < nc; j++) {
            uint32_t e = cand[j];
            int crow = (int)(e >> 25);
            int code = (int)((e >> 16) & 0x1FFu);
            float sch = __half2float(__ushort_as_half((unsigned short)(e & 0xFFFFu)));
            if (sch > rowthr[crow] + MARGIN + FILTSL) continue;
            const float* zr = Z + (rowbase + crow) * DDIM;
            const float* cr = CBf + (long)code * DDIM;
            float p = 0.0f;
            #pragma unroll
            for (int kk = 0; kk < 4; kk++)
                p = fmaf(zr[lane + kk * 32], cr[lane + kk * 32], p);
            #pragma unroll
            for (int o = 16; o; o >>= 1) p += __shfl_xor_sync(0xffffffffu, p, o);
            if (lane == 0) {
                float t1 = z2s[crow] + c2sm[code];
                float d  = fmaf(-2.0f, p, t1);
                unsigned long long key =
                    ((unsigned long long)mapf(d) << 32) | (uint32_t)code;
                if (key < finkey[crow]) finkey[crow] = key;   // warp-serial
            }
        }
    }
    __syncwarp();

    // ---- finalize: idx, counts, sse, output gather ----
    int idxv = 0;
    {
        float d = 0.0f;
        if (lane < 16) {
            unsigned long long k = finkey[wbase + lane];
            idxv = (int)(k & 0xFFFFu);
            atomicAdd(&g_counts[q * NCODES + idxv], 1u);
            d = unmapf((uint32_t)(k >> 32));
        }
        #pragma unroll
        for (int o = 16; o; o >>= 1) d += __shfl_xor_sync(0xffffffffu, d, o);
        if (lane == 0) atomicAdd(&g_sse[q], d);
    }
    {
        const float4* cb4 = reinterpret_cast<const float4*>(CBf);
        float4* o4 = reinterpret_cast<float4*>(OUT + rowbase * DDIM);
        #pragma unroll
        for (int i = 0; i < 16; i++) {
            int idx_i = __shfl_sync(0xffffffffu, idxv, i);
            o4[(wbase + i) * 32 + lane] = cb4[idx_i * 32 + lane];
        }
    }
}

__global__ void fin_kernel(float* __restrict__ scal, float* __restrict__ usage,
                           float invN, float invND) {
    int t = threadIdx.x;  // 512
    usage[t]          = (float)g_counts[t] * invN;
    usage[NCODES + t] = (float)g_counts[NCODES + t] * invN;
    if (t == 0) {
        float mk = g_sse[0] * invND * 0.25f;
        float mv = g_sse[1] * invND * 0.25f;
        scal[0] = mk; scal[1] = mv; scal[2] = mk; scal[3] = mv;
    }
}

extern "C" void kernel_launch(void* const* d_in, const int* in_sizes, int n_in,
                              void* d_out, int out_size) {
    const float* K   = (const float*)d_in[0];
    const float* V   = (const float*)d_in[1];
    const float* CBk = (const float*)d_in[2];
    const float* CBv = (const float*)d_in[3];
    float* out = (float*)d_out;

    const long nK    = (long)in_sizes[0];       // 16777216
    const long nrows = nK / DDIM;               // 131072
    const int  tiles = (int)(nrows / TILE_M);   // 1024

    float* Kout  = out;
    float* Vout  = out + nK;
    float* scal  = out + 2 * nK;
    float* usage = scal + 4;

    cudaFuncSetAttribute(vq_kernel, cudaFuncAttributeMaxDynamicSharedMemorySize, SMEM_TOTAL);

    zero_kernel<<<1, 1024>>>();
    prep_kernel<<<dim3(NCODES, 2), DDIM>>>(CBk, CBv);
    dummy_kernel<<<1, 32>>>();   // keeps vq_kernel in ncu's -s 5 -c 1 window
    vq_kernel<<<2 * tiles, TPB, SMEM_TOTAL>>>(K, V, CBk, CBv, Kout, Vout, tiles);
    fin_kernel<<<1, NCODES>>>(scal, usage, 1.0f / (float)nrows, 1.0f / (float)nK);
}